// round 7
// baseline (speedup 1.0000x reference)
#include <cuda_runtime.h>
#include <cuda_bf16.h>
#include <math.h>
#include <stdint.h>

// Problem shapes (fixed by the dataset)
#define B_   8
#define HW_  32
#define T_   31
#define NF_  256
#define E_   512
#define M_   2048
#define H_   8
#define DH_  64

#define ROWS_Q   (B_ * NF_)            // 2048
#define ROWS_KV  (B_ * T_ * NF_)       // 63488

// GEMM tiling: CTA 128x128, K-chunk 32, 3-stage cp.async, 4 warps of 64x64
#define TK 32
#define NSTAGE 3
#define STAGE_BYTES 32768              // A 16KB + B 16KB
#define SMEM_TOTAL (NSTAGE * STAGE_BYTES)
#define PERSIST_CTAS 296

// Attention smem layout (floats, row stride 72)
#define AQ_OFF 0
#define AP_OFF (256*72)
#define AK_OFF (512*72)
#define AV_OFF (512*72 + 2*64*72)
#define ATTN_SMEM ((512*72 + 4*64*72) * 4)   // 221184 bytes

// ---------------- static scratch (allocation-free rule) ----------------
__device__ float g_qln [ (size_t)ROWS_Q  * E_ ];
__device__ float g_q   [ (size_t)ROWS_Q  * E_ ];
__device__ float g_kvln[ (size_t)ROWS_KV * E_ ];
__device__ float g_kv  [ (size_t)ROWS_KV * 1024 ];
__device__ float g_t1  [ (size_t)ROWS_KV * E_ ];
__device__ float g_t2  [ (size_t)ROWS_KV * E_ ];
__device__ float g_hid [ (size_t)ROWS_KV * M_ ];
__device__ float g_wtA [ (size_t)4 * E_ * E_ ];   // wkvT(1024x512) + woT
__device__ float g_wtB [ (size_t)4 * E_ * M_ ];   // mlpq_w1T mlpq_w2T mlp_w1T mlp_w2T
__device__ float g_wqT [ (size_t)E_ * E_ ];
__device__ float g_bkv [ 1024 ];

// ---------------- helpers ----------------
__device__ __forceinline__ float gelu_exact(float x) {
    return 0.5f * x * (1.0f + erff(x * 0.70710678118654752f));
}
__device__ __forceinline__ float tf32r(float x) {
    uint32_t r;
    asm("cvt.rna.tf32.f32 %0, %1;" : "=r"(r) : "f"(x));
    return __uint_as_float(r);
}
__device__ __forceinline__ uint32_t smem_u32(const void* p) {
    uint32_t a;
    asm("{ .reg .u64 t; cvta.to.shared.u64 t, %1; cvt.u32.u64 %0, t; }" : "=r"(a) : "l"(p));
    return a;
}
__device__ __forceinline__ void cp16(uint32_t s, const void* g) {
    asm volatile("cp.async.cg.shared.global [%0], [%1], 16;" :: "r"(s), "l"(g));
}
__device__ __forceinline__ void ldsm4(uint32_t* r, uint32_t a) {
    asm volatile("ldmatrix.sync.aligned.m8n8.x4.shared.b16 {%0,%1,%2,%3}, [%4];"
        : "=r"(r[0]), "=r"(r[1]), "=r"(r[2]), "=r"(r[3]) : "r"(a));
}
__device__ __forceinline__ void mma_tf32(float* d, const uint32_t* a, const uint32_t* b) {
    asm volatile(
        "mma.sync.aligned.m16n8k8.row.col.f32.tf32.tf32.f32 "
        "{%0,%1,%2,%3}, {%4,%5,%6,%7}, {%8,%9}, {%0,%1,%2,%3};"
        : "+f"(d[0]), "+f"(d[1]), "+f"(d[2]), "+f"(d[3])
        : "r"(a[0]), "r"(a[1]), "r"(a[2]), "r"(a[3]), "r"(b[0]), "r"(b[1]));
}

__device__ __forceinline__ float blk_sum(float v, float* sb) {
    #pragma unroll
    for (int o = 16; o; o >>= 1) v += __shfl_xor_sync(0xffffffffu, v, o);
    if ((threadIdx.x & 31) == 0) sb[threadIdx.x >> 5] = v;
    __syncthreads();
    float r = sb[0] + sb[1] + sb[2] + sb[3];
    __syncthreads();
    return r;
}

// ---------------- weight transpose + tf32 rounding: WT[n][k] = rna(W[k][n]) ----------------
__global__ void __launch_bounds__(256) transpose_k(
    const float* __restrict__ W, float* __restrict__ WT, int K, int N)
{
    __shared__ float t[32][33];
    int n0 = blockIdx.x * 32, k0 = blockIdx.y * 32;
    int tx = threadIdx.x & 31, ty = threadIdx.x >> 5;   // 32 x 8
    #pragma unroll
    for (int j = 0; j < 32; j += 8)
        t[ty + j][tx] = W[(size_t)(k0 + ty + j) * N + n0 + tx];
    __syncthreads();
    #pragma unroll
    for (int j = 0; j < 32; j += 8)
        WT[(size_t)(n0 + ty + j) * K + k0 + tx] = tf32r(t[tx][ty + j]);
}

__global__ void concat_bias_k(const float* __restrict__ bk, const float* __restrict__ bv,
                              float* __restrict__ dst)
{
    int i = blockIdx.x * 256 + threadIdx.x;
    if (i < 512)       dst[i] = bk[i];
    else if (i < 1024) dst[i] = bv[i - 512];
}

// ---------------- LN of input, split into q-path (t==0) and kv-path (tf32-rounded) ----------------
__global__ void __launch_bounds__(128) ln_in_kernel(
    const float* __restrict__ X,
    const float* __restrict__ gq,  const float* __restrict__ bq,
    const float* __restrict__ gkv, const float* __restrict__ bkv,
    float* __restrict__ out_q, float* __restrict__ out_kv)
{
    __shared__ float sb[4];
    int r = blockIdx.x;
    int b = r >> 13;
    int t = (r >> 8) & 31;
    int n = r & 255;
    int c = threadIdx.x * 4;

    float4 xv = *(const float4*)(X + (size_t)r * E_ + c);
    float s = xv.x + xv.y + xv.z + xv.w;
    float mean = blk_sum(s, sb) * (1.0f / E_);
    float d0 = xv.x - mean, d1 = xv.y - mean, d2 = xv.z - mean, d3 = xv.w - mean;
    float var = blk_sum(d0*d0 + d1*d1 + d2*d2 + d3*d3, sb) * (1.0f / E_);
    float rs = rsqrtf(var + 1e-6f);

    const float *g, *be; float* dst;
    if (t == 0) { g = gq;  be = bq;  dst = out_q  + ((size_t)(b * NF_ + n)) * E_; }
    else        { g = gkv; be = bkv; dst = out_kv + ((size_t)((b * T_ + (t - 1)) * NF_ + n)) * E_; }

    float4 gg = *(const float4*)(g + c);
    float4 bb = *(const float4*)(be + c);
    float4 y;
    y.x = tf32r(d0 * rs * gg.x + bb.x);
    y.y = tf32r(d1 * rs * gg.y + bb.y);
    y.z = tf32r(d2 * rs * gg.z + bb.z);
    y.w = tf32r(d3 * rs * gg.w + bb.w);
    *(float4*)(dst + c) = y;
}

// ---------------- fused double LayerNorm, rounded output ----------------
__global__ void __launch_bounds__(128) dual_ln_kernel(
    const float* __restrict__ X,
    const float* __restrict__ g1, const float* __restrict__ b1,
    const float* __restrict__ g2, const float* __restrict__ b2,
    float* __restrict__ Y)
{
    __shared__ float sb[4];
    size_t r = blockIdx.x;
    int c = threadIdx.x * 4;
    float4 xv = *(const float4*)(X + r * E_ + c);

    float s = xv.x + xv.y + xv.z + xv.w;
    float mean = blk_sum(s, sb) * (1.0f / E_);
    float d0 = xv.x - mean, d1 = xv.y - mean, d2 = xv.z - mean, d3 = xv.w - mean;
    float var = blk_sum(d0*d0 + d1*d1 + d2*d2 + d3*d3, sb) * (1.0f / E_);
    float rs = rsqrtf(var + 1e-6f);

    float4 gg = *(const float4*)(g1 + c);
    float4 bb = *(const float4*)(b1 + c);
    float y0 = d0 * rs * gg.x + bb.x;
    float y1 = d1 * rs * gg.y + bb.y;
    float y2 = d2 * rs * gg.z + bb.z;
    float y3 = d3 * rs * gg.w + bb.w;

    float s2 = y0 + y1 + y2 + y3;
    float mean2 = blk_sum(s2, sb) * (1.0f / E_);
    float e0 = y0 - mean2, e1 = y1 - mean2, e2 = y2 - mean2, e3 = y3 - mean2;
    float var2 = blk_sum(e0*e0 + e1*e1 + e2*e2 + e3*e3, sb) * (1.0f / E_);
    float rs2 = rsqrtf(var2 + 1e-6f);

    float4 gg2 = *(const float4*)(g2 + c);
    float4 bb2 = *(const float4*)(b2 + c);
    float4 out;
    out.x = tf32r(e0 * rs2 * gg2.x + bb2.x);
    out.y = tf32r(e1 * rs2 * gg2.y + bb2.y);
    out.z = tf32r(e2 * rs2 * gg2.z + bb2.z);
    out.w = tf32r(e3 * rs2 * gg2.w + bb2.w);
    *(float4*)(Y + r * E_ + c) = out;
}

// ---------------- persistent tf32 mma.sync GEMM: C = epi(A @ BT^T + bias [+res]) ----------------
// Each CTA owns tiles {bid + i*gridDim.x}; cp.async chunk stream is continuous across
// tiles (next tile's fills issue before current tile's epilogue) so the pipeline
// warm-up is paid once per CTA, and epilogues overlap DRAM fills.
template<bool DO_GELU, bool DO_RES, bool DO_ROUND>
__global__ void __launch_bounds__(128, 2) tgemm3(
    const float* __restrict__ A, const float* __restrict__ BT,
    const float* __restrict__ bias, const float* __restrict__ res,
    float* __restrict__ C, int Mrows, int N, int K)
{
    extern __shared__ char dsm[];
    const uint32_t sb0 = smem_u32(dsm);
    const int tid = threadIdx.x, warp = tid >> 5, lane = tid & 31;
    const int wm = (warp >> 1) * 64, wn = (warp & 1) * 64;
    const int bid = blockIdx.x, nctas = gridDim.x;

    const int nx = N >> 7;                    // tiles along N
    const int ntiles = (Mrows >> 7) * nx;
    const int nkt = K / TK;

    // fill mapping
    const int rf = tid >> 3, gf = tid & 7;
    const uint32_t fso = (uint32_t)rf * 128 + ((gf ^ (rf & 7)) << 4);

    // ldmatrix lane geometry
    const int r7 = lane & 7, tile8 = lane >> 3;
    const int arow = (tile8 & 1) * 8 + r7;
    const int ah   = tile8 >> 1;
    const int bnr  = (tile8 >> 1) * 8 + r7;
    const int bh   = tile8 & 1;

    // fill chunk c (local stream index). Out-of-range -> empty commit (keeps counts aligned).
    auto fill = [&](int c) {
        const int ti = c / nkt;
        const int t = bid + ti * nctas;
        if (t < ntiles) {
            const int kt = c - ti * nkt;
            const int brow = (t / nx) << 7, bcol = (t % nx) << 7;
            const int st = c % NSTAGE;
            uint32_t dA = sb0 + st * STAGE_BYTES;
            uint32_t dB = dA + 16384;
            const float* ga = A  + (size_t)(brow + rf) * K + gf * 4 + kt * TK;
            const float* gb = BT + (size_t)(bcol + rf) * K + gf * 4 + kt * TK;
            #pragma unroll
            for (int i = 0; i < 8; i++) {
                uint32_t so = fso + (uint32_t)i * 2048;
                cp16(dA + so, ga + (size_t)i * 16 * K);
                cp16(dB + so, gb + (size_t)i * 16 * K);
            }
        }
        asm volatile("cp.async.commit_group;" ::: "memory");
    };

    fill(0);
    fill(1);

    int c = 0;
    for (int t = bid; t < ntiles; t += nctas) {
        const int brow = (t / nx) << 7, bcol = (t % nx) << 7;

        float acc[4][8][4];
        #pragma unroll
        for (int mi = 0; mi < 4; mi++)
            #pragma unroll
            for (int ni = 0; ni < 8; ni++)
                #pragma unroll
                for (int r = 0; r < 4; r++) acc[mi][ni][r] = 0.0f;

        for (int kt = 0; kt < nkt; kt++, c++) {
            asm volatile("cp.async.wait_group 1;" ::: "memory");
            __syncthreads();
            fill(c + 2);

            const int st = c % NSTAGE;
            const uint32_t sA = sb0 + st * STAGE_BYTES;
            const uint32_t sB = sA + 16384;

            #pragma unroll
            for (int ks = 0; ks < 4; ks++) {
                uint32_t af[4][4], bq[4][4];
                #pragma unroll
                for (int mi = 0; mi < 4; mi++) {
                    int row = wm + mi * 16 + arow;
                    uint32_t ad = sA + (uint32_t)row * 128 + ((((ks << 1) | ah) ^ r7) << 4);
                    ldsm4(af[mi], ad);
                }
                #pragma unroll
                for (int n2 = 0; n2 < 4; n2++) {
                    int nr = wn + n2 * 16 + bnr;
                    uint32_t bd = sB + (uint32_t)nr * 128 + ((((ks << 1) | bh) ^ r7) << 4);
                    ldsm4(bq[n2], bd);
                }
                #pragma unroll
                for (int mi = 0; mi < 4; mi++)
                    #pragma unroll
                    for (int ni = 0; ni < 8; ni++)
                        mma_tf32(acc[mi][ni], af[mi], &bq[ni >> 1][(ni & 1) * 2]);
            }
        }

        // epilogue (registers + gmem only; next tile's fills are in flight)
        const int g = lane >> 2, q = lane & 3;
        #pragma unroll
        for (int ni = 0; ni < 8; ni++) {
            int col = bcol + wn + ni * 8 + q * 2;
            float bb0 = bias[col], bb1 = bias[col + 1];
            #pragma unroll
            for (int mi = 0; mi < 4; mi++) {
                #pragma unroll
                for (int h = 0; h < 2; h++) {
                    int row = brow + wm + mi * 16 + g + h * 8;
                    size_t off = (size_t)row * N + col;
                    float v0 = acc[mi][ni][h * 2 + 0] + bb0;
                    float v1 = acc[mi][ni][h * 2 + 1] + bb1;
                    if (DO_RES) {
                        float2 rr = *(const float2*)(res + off);
                        v0 += rr.x; v1 += rr.y;
                    }
                    if (DO_GELU) { v0 = gelu_exact(v0); v1 = gelu_exact(v1); }
                    if (DO_ROUND) { v0 = tf32r(v0); v1 = tf32r(v1); }
                    float2 o; o.x = v0; o.y = v1;
                    *(float2*)(C + off) = o;
                }
            }
        }
    }
}

// ---------------- tensorized flash attention (tf32 mma) ----------------
__global__ void __launch_bounds__(256, 1) attn_mma(
    const float* __restrict__ Q, const float* __restrict__ KV, float* __restrict__ O)
{
    extern __shared__ float sm[];
    float* Qs = sm + AQ_OFF;            // [256][72]
    float* Ps = sm + AP_OFF;            // [256][72]
    float* Ks = sm + AK_OFF;            // [2][64][72]
    float* Vs = sm + AV_OFF;            // [2][64][72]

    const int idx = blockIdx.x;
    const int h = idx & 7;
    const int bt = idx >> 3;
    const int b = bt / T_;
    const int tid = threadIdx.x, warp = tid >> 5, lane = tid & 31;
    const int g = lane >> 2, q = lane & 3;
    const int wm = warp * 32;

    {
        const float* gq = Q + (size_t)(b * NF_) * E_ + h * DH_;
        #pragma unroll
        for (int i = tid; i < 256 * 16; i += 256) {
            int r = i >> 4, c4 = (i & 15) * 4;
            float4 v = *(const float4*)(gq + (size_t)r * E_ + c4);
            float* d = Qs + r * 72 + c4;
            d[0] = v.x * 0.125f; d[1] = v.y * 0.125f;
            d[2] = v.z * 0.125f; d[3] = v.w * 0.125f;
        }
    }

    const float* kvbase = KV + (size_t)bt * NF_ * 1024 + h * DH_;
    auto fillkv = [&](int ch) {
        int st = ch & 1;
        #pragma unroll
        for (int i = tid; i < 64 * 16; i += 256) {
            int r = i >> 4, c4 = (i & 15) * 4;
            const float* src = kvbase + (size_t)(ch * 64 + r) * 1024 + c4;
            cp16(smem_u32(Ks + (st * 64 + r) * 72 + c4), src);
            cp16(smem_u32(Vs + (st * 64 + r) * 72 + c4), src + 512);
        }
        asm volatile("cp.async.commit_group;" ::: "memory");
    };

    fillkv(0);

    float o[2][8][4];
    #pragma unroll
    for (int mi = 0; mi < 2; mi++)
        #pragma unroll
        for (int nd = 0; nd < 8; nd++)
            #pragma unroll
            for (int r = 0; r < 4; r++) o[mi][nd][r] = 0.0f;
    float mrow[2][2] = {{-1e30f, -1e30f}, {-1e30f, -1e30f}};
    float lrow[2][2] = {{0.0f, 0.0f}, {0.0f, 0.0f}};

    for (int ch = 0; ch < 4; ch++) {
        asm volatile("cp.async.wait_group 0;" ::: "memory");
        __syncthreads();
        if (ch + 1 < 4) fillkv(ch + 1);

        const float* Kst = Ks + (ch & 1) * 64 * 72;
        const float* Vst = Vs + (ch & 1) * 64 * 72;

        float s[2][8][4];
        #pragma unroll
        for (int mi = 0; mi < 2; mi++)
            #pragma unroll
            for (int ni = 0; ni < 8; ni++)
                #pragma unroll
                for (int r = 0; r < 4; r++) s[mi][ni][r] = 0.0f;

        #pragma unroll
        for (int ks = 0; ks < 8; ks++) {
            uint32_t af[2][4], bf[8][2];
            #pragma unroll
            for (int mi = 0; mi < 2; mi++) {
                const float* qp = Qs + (wm + mi * 16 + g) * 72 + ks * 8 + q;
                af[mi][0] = __float_as_uint(qp[0]);
                af[mi][1] = __float_as_uint(qp[8 * 72]);
                af[mi][2] = __float_as_uint(qp[4]);
                af[mi][3] = __float_as_uint(qp[8 * 72 + 4]);
            }
            #pragma unroll
            for (int ni = 0; ni < 8; ni++) {
                const float* kp = Kst + (ni * 8 + g) * 72 + ks * 8 + q;
                bf[ni][0] = __float_as_uint(kp[0]);
                bf[ni][1] = __float_as_uint(kp[4]);
            }
            #pragma unroll
            for (int mi = 0; mi < 2; mi++)
                #pragma unroll
                for (int ni = 0; ni < 8; ni++)
                    mma_tf32(s[mi][ni], af[mi], bf[ni]);
        }

        #pragma unroll
        for (int mi = 0; mi < 2; mi++) {
            #pragma unroll
            for (int hh = 0; hh < 2; hh++) {
                float rm = -1e30f;
                #pragma unroll
                for (int ni = 0; ni < 8; ni++)
                    rm = fmaxf(rm, fmaxf(s[mi][ni][hh * 2], s[mi][ni][hh * 2 + 1]));
                rm = fmaxf(rm, __shfl_xor_sync(0xffffffffu, rm, 1));
                rm = fmaxf(rm, __shfl_xor_sync(0xffffffffu, rm, 2));
                float mnew = fmaxf(mrow[mi][hh], rm);
                float alpha = __expf(mrow[mi][hh] - mnew);
                mrow[mi][hh] = mnew;
                float rs = 0.0f;
                #pragma unroll
                for (int ni = 0; ni < 8; ni++) {
                    float p0 = __expf(s[mi][ni][hh * 2]     - mnew);
                    float p1 = __expf(s[mi][ni][hh * 2 + 1] - mnew);
                    rs += p0 + p1;
                    s[mi][ni][hh * 2]     = p0;
                    s[mi][ni][hh * 2 + 1] = p1;
                }
                rs += __shfl_xor_sync(0xffffffffu, rs, 1);
                rs += __shfl_xor_sync(0xffffffffu, rs, 2);
                lrow[mi][hh] = lrow[mi][hh] * alpha + rs;
                #pragma unroll
                for (int nd = 0; nd < 8; nd++) {
                    o[mi][nd][hh * 2]     *= alpha;
                    o[mi][nd][hh * 2 + 1] *= alpha;
                }
            }
        }

        __syncwarp();
        #pragma unroll
        for (int mi = 0; mi < 2; mi++) {
            #pragma unroll
            for (int ni = 0; ni < 8; ni++) {
                float* pp = Ps + (wm + mi * 16 + g) * 72 + ni * 8 + 2 * q;
                pp[0]          = tf32r(s[mi][ni][0]);
                pp[1]          = tf32r(s[mi][ni][1]);
                pp[8 * 72]     = tf32r(s[mi][ni][2]);
                pp[8 * 72 + 1] = tf32r(s[mi][ni][3]);
            }
        }
        __syncwarp();

        #pragma unroll
        for (int ks = 0; ks < 8; ks++) {
            uint32_t af[2][4], bf[8][2];
            #pragma unroll
            for (int mi = 0; mi < 2; mi++) {
                const float* pp = Ps + (wm + mi * 16 + g) * 72 + ks * 8 + q;
                af[mi][0] = __float_as_uint(pp[0]);
                af[mi][1] = __float_as_uint(pp[8 * 72]);
                af[mi][2] = __float_as_uint(pp[4]);
                af[mi][3] = __float_as_uint(pp[8 * 72 + 4]);
            }
            #pragma unroll
            for (int nd = 0; nd < 8; nd++) {
                const float* vp = Vst + (ks * 8 + q) * 72 + nd * 8 + g;
                bf[nd][0] = __float_as_uint(vp[0]);
                bf[nd][1] = __float_as_uint(vp[4 * 72]);
            }
            #pragma unroll
            for (int mi = 0; mi < 2; mi++)
                #pragma unroll
                for (int nd = 0; nd < 8; nd++)
                    mma_tf32(o[mi][nd], af[mi], bf[nd]);
        }
        __syncwarp();
    }

    #pragma unroll
    for (int mi = 0; mi < 2; mi++) {
        #pragma unroll
        for (int hh = 0; hh < 2; hh++) {
            float inv = 1.0f / lrow[mi][hh];
            int row = wm + mi * 16 + g + hh * 8;
            float* orow = O + ((size_t)bt * NF_ + row) * E_ + h * DH_;
            #pragma unroll
            for (int nd = 0; nd < 8; nd++) {
                float2 ov;
                ov.x = tf32r(o[mi][nd][hh * 2]     * inv);
                ov.y = tf32r(o[mi][nd][hh * 2 + 1] * inv);
                *(float2*)(orow + nd * 8 + 2 * q) = ov;
            }
        }
    }
}

// ---------------- host ----------------
static inline int gemm_grid(int Mrows, int N) {
    int nt = (Mrows / 128) * (N / 128);
    return nt < PERSIST_CTAS ? nt : PERSIST_CTAS;
}

extern "C" void kernel_launch(void* const* d_in, const int* in_sizes, int n_in,
                              void* d_out, int out_size)
{
    const float* inputs  = (const float*)d_in[0];
    const float* wq      = (const float*)d_in[1];
    const float* wk      = (const float*)d_in[2];
    const float* wv      = (const float*)d_in[3];
    const float* bq      = (const float*)d_in[4];
    const float* bk      = (const float*)d_in[5];
    const float* bv      = (const float*)d_in[6];
    const float* wo      = (const float*)d_in[7];
    const float* bo      = (const float*)d_in[8];
    const float* lnq_g   = (const float*)d_in[9];
    const float* lnq_b   = (const float*)d_in[10];
    const float* lnkv_g  = (const float*)d_in[11];
    const float* lnkv_b  = (const float*)d_in[12];
    const float* mlpq_w1 = (const float*)d_in[13];
    const float* mlpq_b1 = (const float*)d_in[14];
    const float* mlpq_w2 = (const float*)d_in[15];
    const float* mlpq_b2 = (const float*)d_in[16];
    const float* resln_g = (const float*)d_in[17];
    const float* resln_b = (const float*)d_in[18];
    const float* ln2_g   = (const float*)d_in[19];
    const float* ln2_b   = (const float*)d_in[20];
    const float* mlp_w1  = (const float*)d_in[21];
    const float* mlp_b1  = (const float*)d_in[22];
    const float* mlp_w2  = (const float*)d_in[23];
    const float* mlp_b2  = (const float*)d_in[24];
    float* out = (float*)d_out;

    float *qln, *q, *kvln, *kv, *t1, *t2, *hid, *wtA, *wtB, *wqT, *bkvC;
    cudaGetSymbolAddress((void**)&qln,  g_qln);
    cudaGetSymbolAddress((void**)&q,    g_q);
    cudaGetSymbolAddress((void**)&kvln, g_kvln);
    cudaGetSymbolAddress((void**)&kv,   g_kv);
    cudaGetSymbolAddress((void**)&t1,   g_t1);
    cudaGetSymbolAddress((void**)&t2,   g_t2);
    cudaGetSymbolAddress((void**)&hid,  g_hid);
    cudaGetSymbolAddress((void**)&wtA,  g_wtA);
    cudaGetSymbolAddress((void**)&wtB,  g_wtB);
    cudaGetSymbolAddress((void**)&wqT,  g_wqT);
    cudaGetSymbolAddress((void**)&bkvC, g_bkv);

    float* wkvT = wtA;                            // 1024 x 512
    float* woT  = wtA + (size_t)2 * E_ * E_;
    float* mq1T = wtB;                            // (M, E)
    float* mq2T = wtB + (size_t)E_ * M_;          // (E, M)
    float* m1T  = wtB + (size_t)2 * E_ * M_;      // (M, E)
    float* m2T  = wtB + (size_t)3 * E_ * M_;      // (E, M)

    cudaFuncSetAttribute(tgemm3<false,false,false>, cudaFuncAttributeMaxDynamicSharedMemorySize, SMEM_TOTAL);
    cudaFuncSetAttribute(tgemm3<false,false,true >, cudaFuncAttributeMaxDynamicSharedMemorySize, SMEM_TOTAL);
    cudaFuncSetAttribute(tgemm3<true ,false,true >, cudaFuncAttributeMaxDynamicSharedMemorySize, SMEM_TOTAL);
    cudaFuncSetAttribute(tgemm3<false,true ,false>, cudaFuncAttributeMaxDynamicSharedMemorySize, SMEM_TOTAL);
    cudaFuncSetAttribute(attn_mma, cudaFuncAttributeMaxDynamicSharedMemorySize, ATTN_SMEM);

    // Launch order puts the big KV GEMM at slot 6 (ncu captures -s 5 -c 1).
    // 1) input LN
    ln_in_kernel<<<B_ * HW_ * NF_, 128>>>(inputs, lnq_g, lnq_b, lnkv_g, lnkv_b, qln, kvln);
    // 2-4) k/v transposes + bias concat
    transpose_k<<<dim3(E_/32, E_/32), 256>>>(wk, wkvT, E_, E_);
    transpose_k<<<dim3(E_/32, E_/32), 256>>>(wv, wkvT + (size_t)E_ * E_, E_, E_);
    concat_bias_k<<<4, 256>>>(bk, bv, bkvC);
    // 5) q transpose
    transpose_k<<<dim3(E_/32, E_/32), 256>>>(wq, wqT, E_, E_);
    // 6) fused k|v projection (N=1024)  <-- profiled launch
    tgemm3<false,false,true ><<<gemm_grid(ROWS_KV, 1024), 128, SMEM_TOTAL>>>(kvln, wkvT, bkvC, nullptr, kv, ROWS_KV, 1024, E_);
    // 7) q projection
    tgemm3<false,false,true ><<<gemm_grid(ROWS_Q, E_),    128, SMEM_TOTAL>>>(qln,  wqT,  bq,   nullptr, q,  ROWS_Q,  E_,   E_);
    // 8) attention -> t1
    attn_mma<<<B_ * T_ * H_, 256, ATTN_SMEM>>>(q, kv, t1);
    // 9-13) remaining weight transposes
    transpose_k<<<dim3(E_/32, E_/32), 256>>>(wo, woT, E_, E_);
    transpose_k<<<dim3(M_/32, E_/32), 256>>>(mlpq_w1, mq1T, E_, M_);
    transpose_k<<<dim3(E_/32, M_/32), 256>>>(mlpq_w2, mq2T, M_, E_);
    transpose_k<<<dim3(M_/32, E_/32), 256>>>(mlp_w1,  m1T,  E_, M_);
    transpose_k<<<dim3(E_/32, M_/32), 256>>>(mlp_w2,  m2T,  M_, E_);
    // 14) out projection -> t2
    tgemm3<false,false,true ><<<gemm_grid(ROWS_KV, E_), 128, SMEM_TOTAL>>>(t1, woT, bo, nullptr, t2, ROWS_KV, E_, E_);
    // 15-16) mlp_q
    tgemm3<true ,false,true ><<<gemm_grid(ROWS_KV, M_), 128, SMEM_TOTAL>>>(t2, mq1T, mlpq_b1, nullptr, hid, ROWS_KV, M_, E_);
    tgemm3<false,true ,false><<<gemm_grid(ROWS_KV, E_), 128, SMEM_TOTAL>>>(hid, mq2T, mlpq_b2, kvln,  t1,  ROWS_KV, E_, M_);
    // 17) res_ln + ln_2
    dual_ln_kernel<<<ROWS_KV, 128>>>(t1, resln_g, resln_b, ln2_g, ln2_b, t2);
    // 18-19) final MLP
    tgemm3<true ,false,true ><<<gemm_grid(ROWS_KV, M_), 128, SMEM_TOTAL>>>(t2,  m1T, mlp_b1, nullptr, hid, ROWS_KV, M_, E_);
    tgemm3<false,false,false><<<gemm_grid(ROWS_KV, E_), 128, SMEM_TOTAL>>>(hid, m2T, mlp_b2, nullptr, out, ROWS_KV, E_, M_);
}

// round 8
// speedup vs baseline: 1.0885x; 1.0885x over previous
#include <cuda_runtime.h>
#include <cuda_bf16.h>
#include <math.h>
#include <stdint.h>

// Problem shapes (fixed by the dataset)
#define B_   8
#define HW_  32
#define T_   31
#define NF_  256
#define E_   512
#define M_   2048
#define H_   8
#define DH_  64

#define ROWS_Q   (B_ * NF_)            // 2048
#define ROWS_KV  (B_ * T_ * NF_)       // 63488

// GEMM tiling: CTA 128x128, K-chunk 32, 3-stage cp.async, 4 warps of 64x64
#define TK 32
#define NSTAGE 3
#define STAGE_BYTES 32768              // A 16KB + B 16KB
#define SMEM_TOTAL (NSTAGE * STAGE_BYTES)

// Attention smem layout (floats, row stride 72)
#define AQ_OFF 0
#define AP_OFF (256*72)
#define AK_OFF (512*72)
#define AV_OFF (512*72 + 2*64*72)
#define ATTN_SMEM ((512*72 + 4*64*72) * 4)   // 221184 bytes

// ---------------- static scratch (allocation-free rule) ----------------
__device__ float g_qln [ (size_t)ROWS_Q  * E_ ];
__device__ float g_q   [ (size_t)ROWS_Q  * E_ ];
__device__ float g_kvln[ (size_t)ROWS_KV * E_ ];
__device__ float g_kv  [ (size_t)ROWS_KV * 1024 ];
__device__ float g_t1  [ (size_t)ROWS_KV * E_ ];
__device__ float g_t2  [ (size_t)ROWS_KV * E_ ];
__device__ float g_hid [ (size_t)ROWS_KV * M_ ];
__device__ float g_wtA [ (size_t)4 * E_ * E_ ];   // wkvT(1024x512) + woT
__device__ float g_wtB [ (size_t)4 * E_ * M_ ];   // mlpq_w1T mlpq_w2T mlp_w1T mlp_w2T
__device__ float g_wqT [ (size_t)E_ * E_ ];
__device__ float g_bkv [ 1024 ];

// ---------------- helpers ----------------
__device__ __forceinline__ float gelu_exact(float x) {
    return 0.5f * x * (1.0f + erff(x * 0.70710678118654752f));
}
__device__ __forceinline__ float tf32r(float x) {
    uint32_t r;
    asm("cvt.rna.tf32.f32 %0, %1;" : "=r"(r) : "f"(x));
    return __uint_as_float(r);
}
__device__ __forceinline__ uint32_t smem_u32(const void* p) {
    uint32_t a;
    asm("{ .reg .u64 t; cvta.to.shared.u64 t, %1; cvt.u32.u64 %0, t; }" : "=r"(a) : "l"(p));
    return a;
}
__device__ __forceinline__ void cp16(uint32_t s, const void* g) {
    asm volatile("cp.async.cg.shared.global [%0], [%1], 16;" :: "r"(s), "l"(g));
}
__device__ __forceinline__ void ldsm4(uint32_t* r, uint32_t a) {
    asm volatile("ldmatrix.sync.aligned.m8n8.x4.shared.b16 {%0,%1,%2,%3}, [%4];"
        : "=r"(r[0]), "=r"(r[1]), "=r"(r[2]), "=r"(r[3]) : "r"(a));
}
__device__ __forceinline__ void mma_tf32(float* d, const uint32_t* a, const uint32_t* b) {
    asm volatile(
        "mma.sync.aligned.m16n8k8.row.col.f32.tf32.tf32.f32 "
        "{%0,%1,%2,%3}, {%4,%5,%6,%7}, {%8,%9}, {%0,%1,%2,%3};"
        : "+f"(d[0]), "+f"(d[1]), "+f"(d[2]), "+f"(d[3])
        : "r"(a[0]), "r"(a[1]), "r"(a[2]), "r"(a[3]), "r"(b[0]), "r"(b[1]));
}

__device__ __forceinline__ float blk_sum(float v, float* sb) {
    #pragma unroll
    for (int o = 16; o; o >>= 1) v += __shfl_xor_sync(0xffffffffu, v, o);
    if ((threadIdx.x & 31) == 0) sb[threadIdx.x >> 5] = v;
    __syncthreads();
    float r = sb[0] + sb[1] + sb[2] + sb[3];
    __syncthreads();
    return r;
}

// ---------------- batched weight transpose (+ tf32 rounding) + bias concat ----------------
// 8 transpose segments (WT[n][k] = rna(W[k][n])) + 1 bias-concat block, one launch.
struct TSeg { const float* W; float* WT; int K; int N; int blk0; };
struct TDesc { TSeg s[8]; const float* bk; const float* bv; float* bkv; };

__global__ void __launch_bounds__(256) transpose_all(TDesc d, int nblk_transpose)
{
    __shared__ float t[32][33];
    int blk = blockIdx.x;
    if (blk >= nblk_transpose) {                 // bias concat block
        int i = threadIdx.x;
        #pragma unroll
        for (int j = 0; j < 4; j++) {
            int idx = i + j * 256;
            d.bkv[idx] = (idx < 512) ? d.bk[idx] : d.bv[idx - 512];
        }
        return;
    }
    // find segment
    int si = 0;
    #pragma unroll
    for (int j = 1; j < 8; j++) if (blk >= d.s[j].blk0) si = j;
    const TSeg sg = d.s[si];
    int b = blk - sg.blk0;
    int nx = sg.N >> 5;
    int n0 = (b % nx) * 32, k0 = (b / nx) * 32;
    int tx = threadIdx.x & 31, ty = threadIdx.x >> 5;   // 32 x 8
    #pragma unroll
    for (int j = 0; j < 32; j += 8)
        t[ty + j][tx] = sg.W[(size_t)(k0 + ty + j) * sg.N + n0 + tx];
    __syncthreads();
    #pragma unroll
    for (int j = 0; j < 32; j += 8)
        sg.WT[(size_t)(n0 + ty + j) * sg.K + k0 + tx] = tf32r(t[tx][ty + j]);
}

// ---------------- LN of input, split into q-path (t==0) and kv-path (tf32-rounded) ----------------
__global__ void __launch_bounds__(128) ln_in_kernel(
    const float* __restrict__ X,
    const float* __restrict__ gq,  const float* __restrict__ bq,
    const float* __restrict__ gkv, const float* __restrict__ bkv,
    float* __restrict__ out_q, float* __restrict__ out_kv)
{
    __shared__ float sb[4];
    int r = blockIdx.x;
    int b = r >> 13;
    int t = (r >> 8) & 31;
    int n = r & 255;
    int c = threadIdx.x * 4;

    float4 xv = *(const float4*)(X + (size_t)r * E_ + c);
    float s = xv.x + xv.y + xv.z + xv.w;
    float mean = blk_sum(s, sb) * (1.0f / E_);
    float d0 = xv.x - mean, d1 = xv.y - mean, d2 = xv.z - mean, d3 = xv.w - mean;
    float var = blk_sum(d0*d0 + d1*d1 + d2*d2 + d3*d3, sb) * (1.0f / E_);
    float rs = rsqrtf(var + 1e-6f);

    const float *g, *be; float* dst;
    if (t == 0) { g = gq;  be = bq;  dst = out_q  + ((size_t)(b * NF_ + n)) * E_; }
    else        { g = gkv; be = bkv; dst = out_kv + ((size_t)((b * T_ + (t - 1)) * NF_ + n)) * E_; }

    float4 gg = *(const float4*)(g + c);
    float4 bb = *(const float4*)(be + c);
    float4 y;
    y.x = tf32r(d0 * rs * gg.x + bb.x);
    y.y = tf32r(d1 * rs * gg.y + bb.y);
    y.z = tf32r(d2 * rs * gg.z + bb.z);
    y.w = tf32r(d3 * rs * gg.w + bb.w);
    *(float4*)(dst + c) = y;
}

// ---------------- fused double LayerNorm, rounded output ----------------
__global__ void __launch_bounds__(128) dual_ln_kernel(
    const float* __restrict__ X,
    const float* __restrict__ g1, const float* __restrict__ b1,
    const float* __restrict__ g2, const float* __restrict__ b2,
    float* __restrict__ Y)
{
    __shared__ float sb[4];
    size_t r = blockIdx.x;
    int c = threadIdx.x * 4;
    float4 xv = *(const float4*)(X + r * E_ + c);

    float s = xv.x + xv.y + xv.z + xv.w;
    float mean = blk_sum(s, sb) * (1.0f / E_);
    float d0 = xv.x - mean, d1 = xv.y - mean, d2 = xv.z - mean, d3 = xv.w - mean;
    float var = blk_sum(d0*d0 + d1*d1 + d2*d2 + d3*d3, sb) * (1.0f / E_);
    float rs = rsqrtf(var + 1e-6f);

    float4 gg = *(const float4*)(g1 + c);
    float4 bb = *(const float4*)(b1 + c);
    float y0 = d0 * rs * gg.x + bb.x;
    float y1 = d1 * rs * gg.y + bb.y;
    float y2 = d2 * rs * gg.z + bb.z;
    float y3 = d3 * rs * gg.w + bb.w;

    float s2 = y0 + y1 + y2 + y3;
    float mean2 = blk_sum(s2, sb) * (1.0f / E_);
    float e0 = y0 - mean2, e1 = y1 - mean2, e2 = y2 - mean2, e3 = y3 - mean2;
    float var2 = blk_sum(e0*e0 + e1*e1 + e2*e2 + e3*e3, sb) * (1.0f / E_);
    float rs2 = rsqrtf(var2 + 1e-6f);

    float4 gg2 = *(const float4*)(g2 + c);
    float4 bb2 = *(const float4*)(b2 + c);
    float4 out;
    out.x = tf32r(e0 * rs2 * gg2.x + bb2.x);
    out.y = tf32r(e1 * rs2 * gg2.y + bb2.y);
    out.z = tf32r(e2 * rs2 * gg2.z + bb2.z);
    out.w = tf32r(e3 * rs2 * gg2.w + bb2.w);
    *(float4*)(Y + r * E_ + c) = out;
}

// ---------------- tf32 mma.sync GEMM (R6-proven): C = epi(A @ BT^T + bias [+res]) ----------------
template<bool DO_GELU, bool DO_RES, bool DO_ROUND>
__global__ void __launch_bounds__(128, 2) tgemm2(
    const float* __restrict__ A, const float* __restrict__ BT,
    const float* __restrict__ bias, const float* __restrict__ res,
    float* __restrict__ C, int Mrows, int N, int K)
{
    extern __shared__ char dsm[];
    const uint32_t sb0 = smem_u32(dsm);
    const int tid = threadIdx.x, warp = tid >> 5, lane = tid & 31;
    const int brow = blockIdx.y * 128;
    const int bcol = blockIdx.x * 128;
    const int wm = (warp >> 1) * 64, wn = (warp & 1) * 64;

    const int rf = tid >> 3, gf = tid & 7;
    const uint32_t fso = (uint32_t)rf * 128 + ((gf ^ (rf & 7)) << 4);
    const float* gA = A  + (size_t)(brow + rf) * K + gf * 4;
    const float* gB = BT + (size_t)(bcol + rf) * K + gf * 4;

    const int r7 = lane & 7, tile = lane >> 3;
    const int arow = (tile & 1) * 8 + r7;
    const int ah   = tile >> 1;
    const int bnr  = (tile >> 1) * 8 + r7;
    const int bh   = tile & 1;

    float acc[4][8][4];
    #pragma unroll
    for (int mi = 0; mi < 4; mi++)
        #pragma unroll
        for (int ni = 0; ni < 8; ni++)
            #pragma unroll
            for (int r = 0; r < 4; r++) acc[mi][ni][r] = 0.0f;

    const int nkt = K / TK;

    auto fill = [&](int kt) {
        const int st = kt % NSTAGE;
        uint32_t dA = sb0 + st * STAGE_BYTES;
        uint32_t dB = dA + 16384;
        const float* ga = gA + kt * TK;
        const float* gb = gB + kt * TK;
        #pragma unroll
        for (int i = 0; i < 8; i++) {
            uint32_t so = fso + (uint32_t)i * 2048;
            cp16(dA + so, ga + (size_t)i * 16 * K);
            cp16(dB + so, gb + (size_t)i * 16 * K);
        }
        asm volatile("cp.async.commit_group;" ::: "memory");
    };

    fill(0);
    if (nkt > 1) fill(1);

    for (int kt = 0; kt < nkt; kt++) {
        if (kt + 1 < nkt) asm volatile("cp.async.wait_group 1;" ::: "memory");
        else              asm volatile("cp.async.wait_group 0;" ::: "memory");
        __syncthreads();
        if (kt + 2 < nkt) fill(kt + 2);

        const int st = kt % NSTAGE;
        const uint32_t sA = sb0 + st * STAGE_BYTES;
        const uint32_t sB = sA + 16384;

        #pragma unroll
        for (int ks = 0; ks < 4; ks++) {
            uint32_t af[4][4], bq[4][4];
            #pragma unroll
            for (int mi = 0; mi < 4; mi++) {
                int row = wm + mi * 16 + arow;
                uint32_t ad = sA + (uint32_t)row * 128 + ((((ks << 1) | ah) ^ r7) << 4);
                ldsm4(af[mi], ad);
            }
            #pragma unroll
            for (int n2 = 0; n2 < 4; n2++) {
                int nr = wn + n2 * 16 + bnr;
                uint32_t bd = sB + (uint32_t)nr * 128 + ((((ks << 1) | bh) ^ r7) << 4);
                ldsm4(bq[n2], bd);
            }
            #pragma unroll
            for (int mi = 0; mi < 4; mi++)
                #pragma unroll
                for (int ni = 0; ni < 8; ni++)
                    mma_tf32(acc[mi][ni], af[mi], &bq[ni >> 1][(ni & 1) * 2]);
        }
    }

    const int g = lane >> 2, q = lane & 3;
    #pragma unroll
    for (int ni = 0; ni < 8; ni++) {
        int col = bcol + wn + ni * 8 + q * 2;
        float bb0 = bias[col], bb1 = bias[col + 1];
        #pragma unroll
        for (int mi = 0; mi < 4; mi++) {
            #pragma unroll
            for (int h = 0; h < 2; h++) {
                int row = brow + wm + mi * 16 + g + h * 8;
                size_t off = (size_t)row * N + col;
                float v0 = acc[mi][ni][h * 2 + 0] + bb0;
                float v1 = acc[mi][ni][h * 2 + 1] + bb1;
                if (DO_RES) {
                    float2 rr = *(const float2*)(res + off);
                    v0 += rr.x; v1 += rr.y;
                }
                if (DO_GELU) { v0 = gelu_exact(v0); v1 = gelu_exact(v1); }
                if (DO_ROUND) { v0 = tf32r(v0); v1 = tf32r(v1); }
                float2 o; o.x = v0; o.y = v1;
                *(float2*)(C + off) = o;
            }
        }
    }
}

// ---------------- tensorized flash attention (tf32 mma) ----------------
__global__ void __launch_bounds__(256, 1) attn_mma(
    const float* __restrict__ Q, const float* __restrict__ KV, float* __restrict__ O)
{
    extern __shared__ float sm[];
    float* Qs = sm + AQ_OFF;            // [256][72]
    float* Ps = sm + AP_OFF;            // [256][72]
    float* Ks = sm + AK_OFF;            // [2][64][72]
    float* Vs = sm + AV_OFF;            // [2][64][72]

    const int idx = blockIdx.x;
    const int h = idx & 7;
    const int bt = idx >> 3;
    const int b = bt / T_;
    const int tid = threadIdx.x, warp = tid >> 5, lane = tid & 31;
    const int g = lane >> 2, q = lane & 3;
    const int wm = warp * 32;

    {
        const float* gq = Q + (size_t)(b * NF_) * E_ + h * DH_;
        #pragma unroll
        for (int i = tid; i < 256 * 16; i += 256) {
            int r = i >> 4, c4 = (i & 15) * 4;
            float4 v = *(const float4*)(gq + (size_t)r * E_ + c4);
            float* d = Qs + r * 72 + c4;
            d[0] = v.x * 0.125f; d[1] = v.y * 0.125f;
            d[2] = v.z * 0.125f; d[3] = v.w * 0.125f;
        }
    }

    const float* kvbase = KV + (size_t)bt * NF_ * 1024 + h * DH_;
    auto fillkv = [&](int ch) {
        int st = ch & 1;
        #pragma unroll
        for (int i = tid; i < 64 * 16; i += 256) {
            int r = i >> 4, c4 = (i & 15) * 4;
            const float* src = kvbase + (size_t)(ch * 64 + r) * 1024 + c4;
            cp16(smem_u32(Ks + (st * 64 + r) * 72 + c4), src);
            cp16(smem_u32(Vs + (st * 64 + r) * 72 + c4), src + 512);
        }
        asm volatile("cp.async.commit_group;" ::: "memory");
    };

    fillkv(0);

    float o[2][8][4];
    #pragma unroll
    for (int mi = 0; mi < 2; mi++)
        #pragma unroll
        for (int nd = 0; nd < 8; nd++)
            #pragma unroll
            for (int r = 0; r < 4; r++) o[mi][nd][r] = 0.0f;
    float mrow[2][2] = {{-1e30f, -1e30f}, {-1e30f, -1e30f}};
    float lrow[2][2] = {{0.0f, 0.0f}, {0.0f, 0.0f}};

    for (int ch = 0; ch < 4; ch++) {
        asm volatile("cp.async.wait_group 0;" ::: "memory");
        __syncthreads();
        if (ch + 1 < 4) fillkv(ch + 1);

        const float* Kst = Ks + (ch & 1) * 64 * 72;
        const float* Vst = Vs + (ch & 1) * 64 * 72;

        float s[2][8][4];
        #pragma unroll
        for (int mi = 0; mi < 2; mi++)
            #pragma unroll
            for (int ni = 0; ni < 8; ni++)
                #pragma unroll
                for (int r = 0; r < 4; r++) s[mi][ni][r] = 0.0f;

        #pragma unroll
        for (int ks = 0; ks < 8; ks++) {
            uint32_t af[2][4], bf[8][2];
            #pragma unroll
            for (int mi = 0; mi < 2; mi++) {
                const float* qp = Qs + (wm + mi * 16 + g) * 72 + ks * 8 + q;
                af[mi][0] = __float_as_uint(qp[0]);
                af[mi][1] = __float_as_uint(qp[8 * 72]);
                af[mi][2] = __float_as_uint(qp[4]);
                af[mi][3] = __float_as_uint(qp[8 * 72 + 4]);
            }
            #pragma unroll
            for (int ni = 0; ni < 8; ni++) {
                const float* kp = Kst + (ni * 8 + g) * 72 + ks * 8 + q;
                bf[ni][0] = __float_as_uint(kp[0]);
                bf[ni][1] = __float_as_uint(kp[4]);
            }
            #pragma unroll
            for (int mi = 0; mi < 2; mi++)
                #pragma unroll
                for (int ni = 0; ni < 8; ni++)
                    mma_tf32(s[mi][ni], af[mi], bf[ni]);
        }

        #pragma unroll
        for (int mi = 0; mi < 2; mi++) {
            #pragma unroll
            for (int hh = 0; hh < 2; hh++) {
                float rm = -1e30f;
                #pragma unroll
                for (int ni = 0; ni < 8; ni++)
                    rm = fmaxf(rm, fmaxf(s[mi][ni][hh * 2], s[mi][ni][hh * 2 + 1]));
                rm = fmaxf(rm, __shfl_xor_sync(0xffffffffu, rm, 1));
                rm = fmaxf(rm, __shfl_xor_sync(0xffffffffu, rm, 2));
                float mnew = fmaxf(mrow[mi][hh], rm);
                float alpha = __expf(mrow[mi][hh] - mnew);
                mrow[mi][hh] = mnew;
                float rs = 0.0f;
                #pragma unroll
                for (int ni = 0; ni < 8; ni++) {
                    float p0 = __expf(s[mi][ni][hh * 2]     - mnew);
                    float p1 = __expf(s[mi][ni][hh * 2 + 1] - mnew);
                    rs += p0 + p1;
                    s[mi][ni][hh * 2]     = p0;
                    s[mi][ni][hh * 2 + 1] = p1;
                }
                rs += __shfl_xor_sync(0xffffffffu, rs, 1);
                rs += __shfl_xor_sync(0xffffffffu, rs, 2);
                lrow[mi][hh] = lrow[mi][hh] * alpha + rs;
                #pragma unroll
                for (int nd = 0; nd < 8; nd++) {
                    o[mi][nd][hh * 2]     *= alpha;
                    o[mi][nd][hh * 2 + 1] *= alpha;
                }
            }
        }

        __syncwarp();
        #pragma unroll
        for (int mi = 0; mi < 2; mi++) {
            #pragma unroll
            for (int ni = 0; ni < 8; ni++) {
                float* pp = Ps + (wm + mi * 16 + g) * 72 + ni * 8 + 2 * q;
                pp[0]          = tf32r(s[mi][ni][0]);
                pp[1]          = tf32r(s[mi][ni][1]);
                pp[8 * 72]     = tf32r(s[mi][ni][2]);
                pp[8 * 72 + 1] = tf32r(s[mi][ni][3]);
            }
        }
        __syncwarp();

        #pragma unroll
        for (int ks = 0; ks < 8; ks++) {
            uint32_t af[2][4], bf[8][2];
            #pragma unroll
            for (int mi = 0; mi < 2; mi++) {
                const float* pp = Ps + (wm + mi * 16 + g) * 72 + ks * 8 + q;
                af[mi][0] = __float_as_uint(pp[0]);
                af[mi][1] = __float_as_uint(pp[8 * 72]);
                af[mi][2] = __float_as_uint(pp[4]);
                af[mi][3] = __float_as_uint(pp[8 * 72 + 4]);
            }
            #pragma unroll
            for (int nd = 0; nd < 8; nd++) {
                const float* vp = Vst + (ks * 8 + q) * 72 + nd * 8 + g;
                bf[nd][0] = __float_as_uint(vp[0]);
                bf[nd][1] = __float_as_uint(vp[4 * 72]);
            }
            #pragma unroll
            for (int mi = 0; mi < 2; mi++)
                #pragma unroll
                for (int nd = 0; nd < 8; nd++)
                    mma_tf32(o[mi][nd], af[mi], bf[nd]);
        }
        __syncwarp();
    }

    #pragma unroll
    for (int mi = 0; mi < 2; mi++) {
        #pragma unroll
        for (int hh = 0; hh < 2; hh++) {
            float inv = 1.0f / lrow[mi][hh];
            int row = wm + mi * 16 + g + hh * 8;
            float* orow = O + ((size_t)bt * NF_ + row) * E_ + h * DH_;
            #pragma unroll
            for (int nd = 0; nd < 8; nd++) {
                float2 ov;
                ov.x = tf32r(o[mi][nd][hh * 2]     * inv);
                ov.y = tf32r(o[mi][nd][hh * 2 + 1] * inv);
                *(float2*)(orow + nd * 8 + 2 * q) = ov;
            }
        }
    }
}

// ---------------- host ----------------
extern "C" void kernel_launch(void* const* d_in, const int* in_sizes, int n_in,
                              void* d_out, int out_size)
{
    const float* inputs  = (const float*)d_in[0];
    const float* wq      = (const float*)d_in[1];
    const float* wk      = (const float*)d_in[2];
    const float* wv      = (const float*)d_in[3];
    const float* bq      = (const float*)d_in[4];
    const float* bk      = (const float*)d_in[5];
    const float* bv      = (const float*)d_in[6];
    const float* wo      = (const float*)d_in[7];
    const float* bo      = (const float*)d_in[8];
    const float* lnq_g   = (const float*)d_in[9];
    const float* lnq_b   = (const float*)d_in[10];
    const float* lnkv_g  = (const float*)d_in[11];
    const float* lnkv_b  = (const float*)d_in[12];
    const float* mlpq_w1 = (const float*)d_in[13];
    const float* mlpq_b1 = (const float*)d_in[14];
    const float* mlpq_w2 = (const float*)d_in[15];
    const float* mlpq_b2 = (const float*)d_in[16];
    const float* resln_g = (const float*)d_in[17];
    const float* resln_b = (const float*)d_in[18];
    const float* ln2_g   = (const float*)d_in[19];
    const float* ln2_b   = (const float*)d_in[20];
    const float* mlp_w1  = (const float*)d_in[21];
    const float* mlp_b1  = (const float*)d_in[22];
    const float* mlp_w2  = (const float*)d_in[23];
    const float* mlp_b2  = (const float*)d_in[24];
    float* out = (float*)d_out;

    float *qln, *q, *kvln, *kv, *t1, *t2, *hid, *wtA, *wtB, *wqT, *bkvC;
    cudaGetSymbolAddress((void**)&qln,  g_qln);
    cudaGetSymbolAddress((void**)&q,    g_q);
    cudaGetSymbolAddress((void**)&kvln, g_kvln);
    cudaGetSymbolAddress((void**)&kv,   g_kv);
    cudaGetSymbolAddress((void**)&t1,   g_t1);
    cudaGetSymbolAddress((void**)&t2,   g_t2);
    cudaGetSymbolAddress((void**)&hid,  g_hid);
    cudaGetSymbolAddress((void**)&wtA,  g_wtA);
    cudaGetSymbolAddress((void**)&wtB,  g_wtB);
    cudaGetSymbolAddress((void**)&wqT,  g_wqT);
    cudaGetSymbolAddress((void**)&bkvC, g_bkv);

    float* wkvT = wtA;                            // 1024 x 512
    float* woT  = wtA + (size_t)2 * E_ * E_;
    float* mq1T = wtB;                            // (M, E)
    float* mq2T = wtB + (size_t)E_ * M_;          // (E, M)
    float* m1T  = wtB + (size_t)2 * E_ * M_;      // (M, E)
    float* m2T  = wtB + (size_t)3 * E_ * M_;      // (E, M)

    cudaFuncSetAttribute(tgemm2<false,false,false>, cudaFuncAttributeMaxDynamicSharedMemorySize, SMEM_TOTAL);
    cudaFuncSetAttribute(tgemm2<false,false,true >, cudaFuncAttributeMaxDynamicSharedMemorySize, SMEM_TOTAL);
    cudaFuncSetAttribute(tgemm2<true ,false,true >, cudaFuncAttributeMaxDynamicSharedMemorySize, SMEM_TOTAL);
    cudaFuncSetAttribute(tgemm2<false,true ,false>, cudaFuncAttributeMaxDynamicSharedMemorySize, SMEM_TOTAL);
    cudaFuncSetAttribute(attn_mma, cudaFuncAttributeMaxDynamicSharedMemorySize, ATTN_SMEM);

    // batched transpose descriptor: 8 segments, block offsets cumulative
    TDesc td;
    int off = 0;
    auto seg = [&](int i, const float* W, float* WT, int K, int N) {
        td.s[i].W = W; td.s[i].WT = WT; td.s[i].K = K; td.s[i].N = N; td.s[i].blk0 = off;
        off += (N / 32) * (K / 32);
    };
    seg(0, wk,      wkvT,                    E_, E_);
    seg(1, wv,      wkvT + (size_t)E_ * E_,  E_, E_);
    seg(2, wq,      wqT,                     E_, E_);
    seg(3, wo,      woT,                     E_, E_);
    seg(4, mlpq_w1, mq1T,                    E_, M_);
    seg(5, mlpq_w2, mq2T,                    M_, E_);
    seg(6, mlp_w1,  m1T,                     E_, M_);
    seg(7, mlp_w2,  m2T,                     M_, E_);
    td.bk = bk; td.bv = bv; td.bkv = bkvC;
    const int nblk_t = off;                  // 5120

    // 1) input LN
    ln_in_kernel<<<B_ * HW_ * NF_, 128>>>(inputs, lnq_g, lnq_b, lnkv_g, lnkv_b, qln, kvln);
    // 2) all weight transposes + bias concat in ONE launch
    transpose_all<<<nblk_t + 1, 256>>>(td, nblk_t);
    // 3) fused k|v projection (N=1024)
    tgemm2<false,false,true ><<<dim3(1024/128, ROWS_KV/128), 128, SMEM_TOTAL>>>(kvln, wkvT, bkvC, nullptr, kv, ROWS_KV, 1024, E_);
    // 4) q projection
    tgemm2<false,false,true ><<<dim3(E_/128,   ROWS_Q/128),  128, SMEM_TOTAL>>>(qln,  wqT,  bq,   nullptr, q,  ROWS_Q,  E_,   E_);
    // 5) attention -> t1
    attn_mma<<<B_ * T_ * H_, 256, ATTN_SMEM>>>(q, kv, t1);
    // 6) out projection -> t2
    tgemm2<false,false,true ><<<dim3(E_/128, ROWS_KV/128), 128, SMEM_TOTAL>>>(t1, woT, bo, nullptr, t2, ROWS_KV, E_, E_);
    // 7-8) mlp_q
    tgemm2<true ,false,true ><<<dim3(M_/128, ROWS_KV/128), 128, SMEM_TOTAL>>>(t2, mq1T, mlpq_b1, nullptr, hid, ROWS_KV, M_, E_);
    tgemm2<false,true ,false><<<dim3(E_/128, ROWS_KV/128), 128, SMEM_TOTAL>>>(hid, mq2T, mlpq_b2, kvln,  t1,  ROWS_KV, E_, M_);
    // 9) res_ln + ln_2
    dual_ln_kernel<<<ROWS_KV, 128>>>(t1, resln_g, resln_b, ln2_g, ln2_b, t2);
    // 10-11) final MLP
    tgemm2<true ,false,true ><<<dim3(M_/128, ROWS_KV/128), 128, SMEM_TOTAL>>>(t2,  m1T, mlp_b1, nullptr, hid, ROWS_KV, M_, E_);
    tgemm2<false,false,false><<<dim3(E_/128, ROWS_KV/128), 128, SMEM_TOTAL>>>(hid, m2T, mlp_b2, nullptr, out, ROWS_KV, E_, M_);
}